// round 8
// baseline (speedup 1.0000x reference)
#include <cuda_runtime.h>

// Problem constants (match reference)
#define N_ATOMS   245760
#define N_PAIRS   16777216
#define N_MOLS    4096
#define KE_CONST  138.96f

#define BLOCKS    592
#define THREADS   512

// Per-block partial histograms: 592 x 4096 floats = 9.7 MB static scratch.
__device__ float g_part[BLOCKS * N_MOLS];

// ---------------------------------------------------------------------------
// Kernel 1: initialize output with per_system_energy * KE
// ---------------------------------------------------------------------------
__global__ void init_out_kernel(const float* __restrict__ pse,
                                float* __restrict__ out) {
    int m = blockIdx.x * blockDim.x + threadIdx.x;
    if (m < N_MOLS) out[m] = pse[m] * KE_CONST;
}

// ---------------------------------------------------------------------------
// chi(d) with the phi(2d) attenuation folded in
// ---------------------------------------------------------------------------
__device__ __forceinline__ float chi_of_d(float d) {
    // phi(u) = 1 - 6u^5 + 15u^4 - 10u^3, u = 2d, zero for u >= 1
    float u  = 2.0f * d;
    float u2 = u * u;
    float u3 = u2 * u;
    float inner = fmaf(-6.0f, u2, fmaf(15.0f, u, -10.0f));
    float phi   = fmaf(u3, inner, 1.0f);
    phi = (u < 1.0f) ? phi : 0.0f;

    float rs = rsqrtf(fmaf(d, d, 1.0f));   // 1/sqrt(d^2+1)
    float rd = __fdividef(1.0f, d);        // 1/d
    return fmaf(phi, rs - rd, rd);         // rd + phi*(rs-rd)
}

// ---------------------------------------------------------------------------
// Kernel 2: main pair loop — R1 hot loop; epilogue = coalesced STG partials
// ---------------------------------------------------------------------------
__global__ __launch_bounds__(THREADS, 4)
void coulomb_pairs_kernel(const float* __restrict__ q,
                          const int*   __restrict__ idx_i,
                          const int*   __restrict__ idx_j,
                          const float* __restrict__ d_ij,
                          const int*   __restrict__ seg)
{
    __shared__ float acc[N_MOLS];   // 16 KB per-block private histogram

    {
        float4* acc4 = reinterpret_cast<float4*>(acc);
        for (int m = threadIdx.x; m < N_MOLS / 4; m += THREADS)
            acc4[m] = make_float4(0.0f, 0.0f, 0.0f, 0.0f);
    }
    __syncthreads();

    const int nquads = N_PAIRS / 4;
    const int stride = gridDim.x * THREADS;

    for (int t = blockIdx.x * THREADS + threadIdx.x; t < nquads; t += stride) {
        // ---- Streaming loads (evict-first: keep L1 for gathers) ----
        int4   vi = __ldcs(reinterpret_cast<const int4*>(idx_i) + t);
        int4   vj = __ldcs(reinterpret_cast<const int4*>(idx_j) + t);
        float4 vd = __ldcs(reinterpret_cast<const float4*>(d_ij) + t);
        int4   vs = __ldcs(reinterpret_cast<const int4*>(seg)   + t);

        // ---- Batch the 8 random gathers back-to-back (max MLP) ----
        float qi0 = __ldg(q + vi.x), qj0 = __ldg(q + vj.x);
        float qi1 = __ldg(q + vi.y), qj1 = __ldg(q + vj.y);
        float qi2 = __ldg(q + vi.z), qj2 = __ldg(q + vj.z);
        float qi3 = __ldg(q + vi.w), qj3 = __ldg(q + vj.w);

        // ---- Compute ----
        float c0 = qi0 * qj0 * chi_of_d(vd.x);
        float c1 = qi1 * qj1 * chi_of_d(vd.y);
        float c2 = qi2 * qj2 * chi_of_d(vd.z);
        float c3 = qi3 * qj3 * chi_of_d(vd.w);

        // ---- Scatter: single-statement if -> @P ATOMS (no BSSY) ----
        if (vi.x < vj.x) atomicAdd(&acc[vs.x], c0);
        if (vi.y < vj.y) atomicAdd(&acc[vs.y], c1);
        if (vi.z < vj.z) atomicAdd(&acc[vs.z], c2);
        if (vi.w < vj.w) atomicAdd(&acc[vs.w], c3);
    }

    __syncthreads();

    // Epilogue: contention-free coalesced store of this block's partials.
    {
        const float4* acc4 = reinterpret_cast<const float4*>(acc);
        float4* p4 = reinterpret_cast<float4*>(g_part + blockIdx.x * N_MOLS);
        for (int m = threadIdx.x; m < N_MOLS / 4; m += THREADS)
            p4[m] = acc4[m];
    }
}

// ---------------------------------------------------------------------------
// Kernel 3: reduce per-block partials into out (out already holds pse*KE).
// grid = (16, 4): x covers molecules in chunks of 256, y quarters the blocks.
// Consecutive threads read consecutive molecules -> fully coalesced.
// ---------------------------------------------------------------------------
__global__ void reduce_partials_kernel(float* __restrict__ out) {
    int m  = blockIdx.x * 256 + threadIdx.x;
    int b0 = blockIdx.y * (BLOCKS / 4);
    int b1 = b0 + (BLOCKS / 4);

    float s = 0.0f;
    #pragma unroll 4
    for (int b = b0; b < b1; b++)
        s += __ldcs(g_part + b * N_MOLS + m);

    atomicAdd(&out[m], s * KE_CONST);   // 4 adds per molecule total
}

// ---------------------------------------------------------------------------
// Launch
// ---------------------------------------------------------------------------
extern "C" void kernel_launch(void* const* d_in, const int* in_sizes, int n_in,
                              void* d_out, int out_size) {
    const float* q    = (const float*)d_in[0];           // per_atom_charge [N_ATOMS]
    const int*   pidx = (const int*)  d_in[1];           // pair_indices [2, N_PAIRS]
    const float* dij  = (const float*)d_in[2];           // d_ij [N_PAIRS]
    const int*   seg  = (const int*)  d_in[3];           // atomic_subsystem_indices [N_PAIRS]
    const float* pse  = (const float*)d_in[4];           // per_system_energy [N_MOLS]
    float* out = (float*)d_out;

    const int* idx_i = pidx;
    const int* idx_j = pidx + N_PAIRS;

    init_out_kernel<<<(N_MOLS + 255) / 256, 256>>>(pse, out);

    // Proven config: single wave, 4 blocks/SM x 148 SMs, 512 threads.
    coulomb_pairs_kernel<<<BLOCKS, THREADS>>>(q, idx_i, idx_j, dij, seg);

    dim3 rg(N_MOLS / 256, 4);
    reduce_partials_kernel<<<rg, 256>>>(out);
}